// round 12
// baseline (speedup 1.0000x reference)
#include <cuda_runtime.h>
#include <cstdint>

// Problem constants
#define B_    16
#define T_    60
#define N_    196
#define C_    512
#define SEGS_ 10
#define TOPK_ 6
#define TOPM_ 12
#define HEADS_ 4
#define HD_   128
#define CLIP_ 6      // T/SEGS
#define FRAMES_ 36   // CLIP*TOPK
#define SCALE_ 0.08838834764831845f  // 1/sqrt(128)

// Output layout (flattened tuple concat):
//   [0, 294912)              audio_top_k        (B, FRAMES, C)
//   [294912, 3833856)        visual_patch_top_m (B, FRAMES, TOPM, C)
//   [3833856, 7372800)       visual_patch_feat  (B, FRAMES*TOPM, C) == same data
#define OUT_AUDIO_ 0
#define OUT_TOPM_  (B_*FRAMES_*C_)                    // 294912
#define OUT_FEAT_  (OUT_TOPM_ + B_*FRAMES_*TOPM_*C_)  // 3833856

// Block-role layout (single fused kernel, blockDim = 128):
//   [0, 128)       K1: q projection (warp-per-output, 4 outputs/block)
//   [128, 144)     K2: qW (head, 128-col chunk)          spin c_q  == 128
//   [144, 340)     K3a: scores per patch n               spin c_qw == 16
//   [340]          K3b: softmax + mean + top-12 -> pid   spin c_sc == 196
//   [341, 917)     K4-audio: audio gather (no deps)
//   [917, 2069)    K4-patch: broadcast pid patch row     spin flag == 1
// Total 2069 blocks < 2368 wave-1 capacity (148 SM x 16 blocks @ 4 warps)
// => entire grid co-resident; all spin producers provably running.
#define NB_K1_     128
#define NB_K2_     16
#define NB_K3A_    N_
#define B0_K2_     (NB_K1_)                 // 128
#define B0_K3A_    (B0_K2_ + NB_K2_)        // 144
#define B0_K3B_    (B0_K3A_ + NB_K3A_)      // 340
#define B0_AUDIO_  (B0_K3B_ + 1)            // 341
#define NB_AUDIO_  (B_*FRAMES_)             // 576
#define B0_PATCH_  (B0_AUDIO_ + NB_AUDIO_)  // 917
#define NB_PATCH_  (B_*FRAMES_*2)           // 1152 (2 sub-blocks per bf)
#define NB_TOTAL_  (B0_PATCH_ + NB_PATCH_)  // 2069

// Device scratch + sync state (no allocations allowed; reset each run)
__device__ float g_q[C_];              // q projection of qst_feat[0]
__device__ float g_qW[HEADS_*C_];      // qW[h,c]
__device__ float g_scores[HEADS_][N_]; // pre-softmax scores (scaled)
__device__ int   g_pid;
__device__ int   c_q    = 0;           // k1 blocks done (target 128)
__device__ int   c_qw   = 0;           // k2 blocks done (target 16)
__device__ int   c_sc   = 0;           // k3a blocks done (target 196)
__device__ int   g_flag = 0;           // pid ready
__device__ int   c_done = 0;           // k4-patch blocks done (target 1152)

__device__ __forceinline__ void spin_on(volatile int* p, int target) {
    if (threadIdx.x == 0) {
        while (*p != target) __nanosleep(64);
        __threadfence();
    }
    __syncthreads();
}

__device__ __forceinline__ void finish(int* c) {
    __syncthreads();
    if (threadIdx.x == 0) {
        __threadfence();
        atomicAdd(c, 1);
    }
}

__global__ void __launch_bounds__(128)
fused_kernel(const float* __restrict__ audio,
             const float* __restrict__ patch,
             const float* __restrict__ qst,
             const int*   __restrict__ topk,
             const float* __restrict__ in_proj_w,
             const float* __restrict__ in_proj_b,
             float* __restrict__ out) {
    const int bid  = blockIdx.x;
    const int tid  = threadIdx.x;
    const int warp = tid >> 5;
    const int lane = tid & 31;

    if (bid < NB_K1_) {
        // ---- K1: q[j] = dot(qst[0,:], Wq[j,:]) + bq[j]; warp-per-output ----
        int j = bid * 4 + warp;  // 0..511
        const float4* wrow = (const float4*)(in_proj_w + (size_t)j * C_);
        const float4* qv   = (const float4*)qst;
        float acc = 0.f;
        #pragma unroll 4
        for (int i = lane; i < C_ / 4; i += 32) {
            float4 a = wrow[i];
            float4 b = qv[i];
            acc += a.x * b.x + a.y * b.y + a.z * b.z + a.w * b.w;
        }
        #pragma unroll
        for (int o = 16; o; o >>= 1) acc += __shfl_xor_sync(0xffffffffu, acc, o);
        if (lane == 0) g_q[j] = acc + in_proj_b[j];
        finish(&c_q);

    } else if (bid < B0_K3A_) {
        // ---- K2: qW[h,c] = sum_d q[h*HD+d] * Wk[h*HD+d, c] ----
        spin_on(&c_q, NB_K1_);
        int idx = bid - B0_K2_;
        int h = idx >> 2, chunk = idx & 3;
        int c = chunk * 128 + tid;
        __shared__ float sq[HD_];
        sq[tid] = g_q[h * HD_ + tid];
        __syncthreads();
        const float* Wk = in_proj_w + (size_t)C_ * C_;  // rows C..2C
        const float* base = Wk + (size_t)(h * HD_) * C_ + c;
        float acc = 0.f;
        #pragma unroll 8
        for (int d = 0; d < HD_; d++) acc += sq[d] * base[(size_t)d * C_];
        g_qW[h * C_ + c] = acc;
        finish(&c_qw);

    } else if (bid < B0_K3B_) {
        // ---- K3a: scores[h,n] = SCALE * dot(patch[0,frame0,n,:], qW[h,:]) ----
        spin_on(&c_qw, NB_K2_);
        int n = bid - B0_K3A_;
        int frame0 = topk[0] * CLIP_;  // top_k_index_sort[0,0,0] * CLIP, b=0
        const float4* row =
            (const float4*)(patch + (((size_t)frame0 * N_) + n) * C_);
        const float4* wv = (const float4*)(g_qW + warp * C_);
        float acc = 0.f;
        #pragma unroll 4
        for (int i = lane; i < C_ / 4; i += 32) {
            float4 p = row[i];
            float4 w = wv[i];
            acc += p.x * w.x + p.y * w.y + p.z * w.z + p.w * w.w;
        }
        #pragma unroll
        for (int o = 16; o; o >>= 1) acc += __shfl_xor_sync(0xffffffffu, acc, o);
        if (lane == 0) g_scores[warp][n] = acc * SCALE_;
        finish(&c_sc);

    } else if (bid == B0_K3B_) {
        // ---- K3b: softmax per head, mean, top-12 -> pid (register-resident) ----
        spin_on(&c_sc, NB_K3A_);
        __shared__ float w[HEADS_][N_];

        // warp h: softmax of head h, values held in registers (7 per lane)
        float v[7];
        float m = -1e30f;
        #pragma unroll
        for (int j = 0; j < 7; j++) {
            int n = lane + 32 * j;
            v[j] = (n < N_) ? g_scores[warp][n] : -1e30f;
            m = fmaxf(m, v[j]);
        }
        #pragma unroll
        for (int o = 16; o; o >>= 1) m = fmaxf(m, __shfl_xor_sync(0xffffffffu, m, o));
        float sum = 0.f;
        #pragma unroll
        for (int j = 0; j < 7; j++) {
            int n = lane + 32 * j;
            float e = (n < N_) ? expf(v[j] - m) : 0.f;
            v[j] = e;
            sum += e;
        }
        #pragma unroll
        for (int o = 16; o; o >>= 1) sum += __shfl_xor_sync(0xffffffffu, sum, o);
        float inv = 1.f / sum;
        #pragma unroll
        for (int j = 0; j < 7; j++) {
            int n = lane + 32 * j;
            if (n < N_) w[warp][n] = v[j] * inv;
        }
        __syncthreads();

        if (warp == 0) {
            // pw in registers; 12 iterations of warp-argmax (tie -> larger idx)
            float pw[7];
            #pragma unroll
            for (int j = 0; j < 7; j++) {
                int n = lane + 32 * j;
                pw[j] = (n < N_)
                    ? 0.25f * (w[0][n] + w[1][n] + w[2][n] + w[3][n])
                    : -1e30f;
            }
            int pid = -1;
            #pragma unroll
            for (int it = 0; it < TOPM_; it++) {
                float bv = -1e30f;
                int bi = -1;
                #pragma unroll
                for (int j = 0; j < 7; j++) {
                    int n = lane + 32 * j;
                    if (pw[j] > bv || (pw[j] == bv && n > bi)) { bv = pw[j]; bi = n; }
                }
                #pragma unroll
                for (int o = 16; o; o >>= 1) {
                    float ov = __shfl_xor_sync(0xffffffffu, bv, o);
                    int   oi = __shfl_xor_sync(0xffffffffu, bi, o);
                    if (ov > bv || (ov == bv && oi > bi)) { bv = ov; bi = oi; }
                }
                // all lanes agree on bi; owning lane retires it
                if ((bi & 31) == lane) pw[bi >> 5] = -1e30f;
                if (bi > pid) pid = bi;
            }
            if (lane == 0) {
                g_pid = pid;
                __threadfence();
                atomicExch(&g_flag, 1);
            }
        }

    } else if (bid < B0_PATCH_) {
        // ---- K4-audio: gather one audio row (independent of pid) ----
        int bf = bid - B0_AUDIO_;
        int b = bf / FRAMES_, f = bf % FRAMES_;
        int fk = f / CLIP_, cc = f % CLIP_;
        int seg = topk[b * TOPK_ + fk];
        int frame = seg * CLIP_ + cc;
        float4 a = ((const float4*)(audio + ((size_t)b * T_ + frame) * C_))[tid];
        ((float4*)(out + OUT_AUDIO_ + (size_t)bf * C_))[tid] = a;

    } else {
        // ---- K4-patch: broadcast pid patch row (6 TOPM rows x 2 outputs) ----
        spin_on(&g_flag, 1);
        int idx = bid - B0_PATCH_;
        int bf = idx >> 1, sub = idx & 1;
        int b = bf / FRAMES_, f = bf % FRAMES_;
        int fk = f / CLIP_, cc = f % CLIP_;
        int seg = topk[b * TOPK_ + fk];
        int frame = seg * CLIP_ + cc;
        int pid = g_pid;

        float4 p = ((const float4*)(patch +
                     (((size_t)b * T_ + frame) * N_ + pid) * C_))[tid];

        float4* s1 = (float4*)(out + OUT_TOPM_ + (size_t)bf * TOPM_ * C_);
        float4* s2 = (float4*)(out + OUT_FEAT_ + (size_t)bf * TOPM_ * C_);
        #pragma unroll
        for (int mm = 0; mm < 6; mm++) {
            int mrow = sub * 6 + mm;
            s1[mrow * (C_ / 4) + tid] = p;
            s2[mrow * (C_ / 4) + tid] = p;
        }

        // last patch block resets all sync state for the next (graph) replay
        __syncthreads();
        if (tid == 0) {
            __threadfence();
            int old = atomicAdd(&c_done, 1);
            if (old == NB_PATCH_ - 1) {
                c_q = 0; c_qw = 0; c_sc = 0; g_flag = 0; c_done = 0;
                __threadfence();
            }
        }
    }
}

// ---------------------------------------------------------------------------
extern "C" void kernel_launch(void* const* d_in, const int* in_sizes, int n_in,
                              void* d_out, int out_size) {
    const float* audio_feat = (const float*)d_in[0];   // (B,T,C)
    const float* patch_feat = (const float*)d_in[1];   // (B,T,N,C)
    const float* qst_feat   = (const float*)d_in[2];   // (B,C)
    const int*   topk       = (const int*)d_in[3];     // (B,1,TOPK)
    const float* in_proj_w  = (const float*)d_in[4];   // (3C,C)
    const float* in_proj_b  = (const float*)d_in[5];   // (3C,)
    float* out = (float*)d_out;

    fused_kernel<<<NB_TOTAL_, 128>>>(audio_feat, patch_feat, qst_feat, topk,
                                     in_proj_w, in_proj_b, out);
}